// round 17
// baseline (speedup 1.0000x reference)
#include <cuda_runtime.h>

#define NATOM 24
#define NSP 4
#define OUTW 384          // 64 radial + 320 angular
#define RADW 64
#define CPB 6             // centers per block
#define PARTS 4
#define THREADS 256       // 8 warps
#define NWARP 8
#define CHUNK 192
#define MAXTRI (CPB * 253)

__constant__ float COSZ[8] = {
     0.980785280403230449f,  0.831469612302545237f,  0.555570233019602225f,  0.195090322016128268f,
    -0.195090322016128268f, -0.555570233019602225f, -0.831469612302545237f, -0.980785280403230449f };
__constant__ float SINZ[8] = {
     0.195090322016128268f,  0.555570233019602225f,  0.831469612302545237f,  0.980785280403230449f,
     0.980785280403230449f,  0.831469612302545237f,  0.555570233019602225f,  0.195090322016128268f };

#define PACK_F32X2(out, lo, hi) \
    asm("mov.b64 %0, {%1, %2};" : "=l"(out) : "f"(lo), "f"(hi))
#define UNPACK_F32X2(lo, hi, in) \
    asm("mov.b64 {%0, %1}, %2;" : "=f"(lo), "=f"(hi) : "l"(in))
#define MUL_F32X2(out, a, b) \
    asm("mul.rn.f32x2 %0, %1, %2;" : "=l"(out) : "l"(a), "l"(b))

__global__ __launch_bounds__(THREADS)
void aev_kernel(const int* __restrict__ g_species,
                const float* __restrict__ g_coords,
                float* __restrict__ g_out, int M)
{
    const int bid   = blockIdx.x;
    const int m     = bid >> 2;
    const int ibase = (bid & 3) * CPB;

    __shared__ float    sc[NATOM][3];
    __shared__ int      ssp[NATOM];
    __shared__ float    sd  [CPB][NATOM];
    __shared__ float    sfcr[CPB][NATOM];
    __shared__ float4   cu  [CPB * NATOM];     // ux,uy,uz (pre-scaled sqrt(.95)), d
    __shared__ float    cfa [CPB * NATOM];
    __shared__ int      csp [CPB * NATOM];
    __shared__ unsigned short triples[MAXTRI]; // (il<<10)|(a<<5)|b
    __shared__ int      tcnt;
    __shared__ float2   scs [CHUNK + 4];       // c, s
    __shared__ unsigned short soff[CHUNK + 4]; // acc offset (fits 12 bits)
    __shared__ float4   swf [CHUNK + 4];       // folded weights wf[0..3]
    __shared__ __align__(16) float acc[CPB][OUTW];

    const int tid  = threadIdx.x;
    const int lane = tid & 31;
    const int w    = tid >> 5;

    // ---- init -----------------------------------------------------------
    if (tid == 0) tcnt = 0;
    if (tid < NATOM) {
        ssp[tid]   = g_species[m * NATOM + tid];
        sc[tid][0] = g_coords[(m * NATOM + tid) * 3 + 0];
        sc[tid][1] = g_coords[(m * NATOM + tid) * 3 + 1];
        sc[tid][2] = g_coords[(m * NATOM + tid) * 3 + 2];
    }
    for (int idx = tid; idx < CPB * OUTW; idx += THREADS)
        ((float*)acc)[idx] = 0.0f;
    __syncthreads();

    // ---- screen + compact + emit: warps 0..5, lane = neighbor j -----------
    if (w < CPB) {
        const int ic = ibase + w;
        bool  live = false;
        float fca = 0.f, d = 1.f, dx = 0.f, dy = 0.f, dz = 0.f;
        if (lane < NATOM) {
            int j = lane;
            dx = sc[j][0] - sc[ic][0];
            dy = sc[j][1] - sc[ic][1];
            dz = sc[j][2] - sc[ic][2];
            float d2 = dx * dx + dy * dy + dz * dz;
            bool ok = (j != ic);
            d = ok ? sqrtf(d2) : 1.0f;
            fca       = (ok && d <= 3.5f) ? (0.5f * __cosf(0.897597901025655210f * d) + 0.5f) : 0.0f;
            float fcr = (ok && d <= 5.2f) ? (0.5f * __cosf(0.604152493782718100f * d) + 0.5f) : 0.0f;
            sd[w][j]   = d;
            sfcr[w][j] = fcr;
            live = (fca > 0.0f);
        }
        unsigned mask = __ballot_sync(0xffffffffu, live);
        int nn = __popc(mask);
        if (live) {
            int pos = __popc(mask & ((1u << lane) - 1u));
            float rd = 0.97467943448089633f / d;   // fold sqrt(0.95)
            cu [w * NATOM + pos] = make_float4(dx * rd, dy * rd, dz * rd, d);
            cfa[w * NATOM + pos] = fca;
            csp[w * NATOM + pos] = ssp[lane];
        }
        __syncwarp();

        int npairs = (nn * (nn - 1)) >> 1;
        int base = 0;
        if (lane == 0 && npairs > 0) base = atomicAdd(&tcnt, npairs);
        base = __shfl_sync(0xffffffffu, base, 0);
        for (int idx = lane; idx < npairs; idx += 32) {
            int a = 0, rem = idx, rowlen = nn - 1;
            while (rem >= rowlen) { rem -= rowlen; rowlen--; a++; }
            int b = a + 1 + rem;
            triples[base + idx] = (unsigned short)((w << 10) | (a << 5) | b);
        }
    }
    __syncthreads();

    // ---- radial: flat over 2304 (pair, shift) tasks on all 8 warps --------
    #pragma unroll
    for (int k = 0; k < (CPB * NATOM * 16) / THREADS; k++) {
        int idx = k * THREADS + tid;
        int p = idx >> 4, r = idx & 15;
        int il = p / NATOM, j = p - il * NATOM;
        float fcr = sfcr[il][j];
        if (fcr > 0.0f) {
            float u = sd[il][j] - (0.9f + 0.26875f * (float)r);
            float v = 0.25f * fcr * __expf(-16.0f * u * u);
            atomicAdd(&acc[il][ssp[j] * 16 + r], v);
        }
    }
    // NOTE: no barrier here — radial touches acc[radial] only, drain phase A
    // reads screen-phase data (synced above), phase B touches acc[angular].

    // ---- chunked block-wide drain -----------------------------------------
    const int NP = tcnt;
    {
        const float czc = 0.5f * COSZ[lane & 7];
        const float szc = 0.5f * SINZ[lane & 7];
        const int   sel = lane >> 3;
        float* accLane = ((float*)acc) + lane;

        for (int chunk = 0; chunk < NP; chunk += CHUNK) {
            const int cnt = min(CHUNK, NP - chunk);

            // phase A: thread = triple; decode 16-bit key, re-derive offset
            if (tid < cnt) {
                unsigned tw = triples[chunk + tid];
                int il = (int)(tw >> 10);
                int a  = (int)((tw >> 5) & 31u);
                int b  = (int)(tw & 31u);
                int ia = il * NATOM + a, ib = il * NATOM + b;
                int spa = csp[ia], spb = csp[ib];
                int lo = min(spa, spb), hi = max(spa, spb);
                int pidx = lo * NSP - ((lo * (lo - 1)) >> 1) + (hi - lo);
                int off = il * OUTW + RADW + pidx * 32;

                float4 ua = cu[ia];
                float4 ub = cu[ib];
                float c = ua.x * ub.x + ua.y * ub.y + ua.z * ub.z;  // 0.95*cos
                float s = sqrtf(fmaxf(0.0f, 1.0f - c * c));
                float davg = 0.5f * (ua.w + ub.w);
                float w2   = 2.0f * cfa[ia] * cfa[ib];
                float u0 = davg - 0.90f;
                float u1 = davg - 1.55f;
                float u2 = davg - 2.20f;
                float u3 = davg - 2.85f;
                float4 wf;
                wf.x = w2 * __expf(-8.0f * u0 * u0);
                wf.y = w2 * __expf(-8.0f * u1 * u1);
                wf.z = w2 * __expf(-8.0f * u2 * u2);
                wf.w = w2 * __expf(-8.0f * u3 * u3);
                scs [tid] = make_float2(c, s);
                soff[tid] = (unsigned short)off;
                swf [tid] = wf;
            }
            if (tid >= cnt && tid < cnt + 4) {   // pad to multiple of 4
                scs [tid] = make_float2(0.f, 0.f);
                soff[tid] = 0;
                swf [tid] = make_float4(0.f, 0.f, 0.f, 0.f);
            }
            __syncthreads();

            const int cntp = (cnt + 3) & ~3;
            // phase B: warp = 4 triples/iter, two packed f32x2 ^32 chains
            for (int t = 4 * w; t < cntp; t += 4 * NWARP) {
                float2 q0 = scs[t],     q1 = scs[t + 1];
                float2 q2 = scs[t + 2], q3 = scs[t + 3];
                float wv0 = ((const float*)&swf[t    ])[sel];
                float wv1 = ((const float*)&swf[t + 1])[sel];
                float wv2 = ((const float*)&swf[t + 2])[sel];
                float wv3 = ((const float*)&swf[t + 3])[sel];
                float cz0 = 0.5f + q0.x * czc + q0.y * szc;
                float cz1 = 0.5f + q1.x * czc + q1.y * szc;
                float cz2 = 0.5f + q2.x * czc + q2.y * szc;
                float cz3 = 0.5f + q3.x * czc + q3.y * szc;
                unsigned long long Pa, Pb;
                PACK_F32X2(Pa, cz0, cz1);
                PACK_F32X2(Pb, cz2, cz3);
                MUL_F32X2(Pa, Pa, Pa);  MUL_F32X2(Pb, Pb, Pb);   // ^2
                MUL_F32X2(Pa, Pa, Pa);  MUL_F32X2(Pb, Pb, Pb);   // ^4
                MUL_F32X2(Pa, Pa, Pa);  MUL_F32X2(Pb, Pb, Pb);   // ^8
                MUL_F32X2(Pa, Pa, Pa);  MUL_F32X2(Pb, Pb, Pb);   // ^16
                MUL_F32X2(Pa, Pa, Pa);  MUL_F32X2(Pb, Pb, Pb);   // ^32
                float x0, x1, x2, x3;
                UNPACK_F32X2(x0, x1, Pa);
                UNPACK_F32X2(x2, x3, Pb);
                atomicAdd(accLane + soff[t],     x0 * wv0);
                atomicAdd(accLane + soff[t + 1], x1 * wv1);
                atomicAdd(accLane + soff[t + 2], x2 * wv2);
                atomicAdd(accLane + soff[t + 3], x3 * wv3);
            }
            __syncthreads();
        }
    }
    __syncthreads();

    // ---- writeout (float4) -----------------------------------------------
    {
        const float4* src = (const float4*)acc;
        float4* dstg = (float4*)(g_out + ((size_t)m * NATOM + ibase) * OUTW);
        #pragma unroll
        for (int idx = tid; idx < CPB * OUTW / 4; idx += THREADS)
            dstg[idx] = src[idx];
    }
}

extern "C" void kernel_launch(void* const* d_in, const int* in_sizes, int n_in,
                              void* d_out, int out_size)
{
    const int*   species = (const int*)d_in[0];
    const float* coords  = (const float*)d_in[1];
    int M = in_sizes[0] / NATOM;
    aev_kernel<<<M * PARTS, THREADS>>>(species, coords, (float*)d_out, M);
}